// round 16
// baseline (speedup 1.0000x reference)
#include <cuda_runtime.h>
#include <cuda_fp16.h>
#include <cstdint>

#define DIMC   768
#define HEADS  12
#define DHC    64
#define BATCH  2
#define SEQ    4096
#define TOKENS (BATCH * SEQ)     // 8192
#define QKVN   (3 * DIMC)        // 2304
#define SCLOG2E 0.05205877693f   // 768^-0.5 * log2(e); folded into Q

// ---------------------------------------------------------------------------
// Scratch (device-code references only). All single fp16.
// ---------------------------------------------------------------------------
__device__ __half g_xh   [(size_t)TOKENS * DIMC];
__device__ __half g_wqkvT[(size_t)QKVN * DIMC];            // [N][K]
__device__ __half g_woutT[(size_t)DIMC * DIMC];
__device__ __half g_qh   [(size_t)BATCH * HEADS * SEQ * DHC];  // Q*SCLOG2E
__device__ __half g_kh   [(size_t)BATCH * HEADS * SEQ * DHC];
__device__ __half g_vth  [(size_t)BATCH * HEADS * DHC * SEQ];  // V^T
__device__ __half g_aoh  [(size_t)TOKENS * DIMC];

// ---------------------------------------------------------------------------
__device__ __forceinline__ uint32_t smem_u32(const void* p) {
    uint32_t a;
    asm("{ .reg .u64 t; cvta.to.shared.u64 t, %1; cvt.u32.u64 %0, t; }"
        : "=r"(a) : "l"(p));
    return a;
}
__device__ __forceinline__ void cp16(uint32_t dst, const void* src) {
    asm volatile("cp.async.cg.shared.global [%0], [%1], 16;"
                 :: "r"(dst), "l"(src));
}
#define CP_COMMIT() asm volatile("cp.async.commit_group;" ::: "memory")
#define CP_WAIT0()  asm volatile("cp.async.wait_group 0;" ::: "memory")
#define CP_WAIT1()  asm volatile("cp.async.wait_group 1;" ::: "memory")
#define CP_WAIT2()  asm volatile("cp.async.wait_group 2;" ::: "memory")

#define LDSM4(R0, R1, R2, R3, ADDR)                                         \
    asm volatile("ldmatrix.sync.aligned.m8n8.x4.shared.b16 "                \
        "{%0,%1,%2,%3}, [%4];"                                              \
        : "=r"(R0), "=r"(R1), "=r"(R2), "=r"(R3) : "r"(ADDR))

__device__ __forceinline__ uint32_t ex2h2(uint32_t y) {
    uint32_t r;
    asm("ex2.approx.f16x2 %0, %1;" : "=r"(r) : "r"(y));
    return r;
}
__device__ __forceinline__ uint32_t pack2h(float x, float y) {
    __half2 t = __floats2half2_rn(x, y);
    return *(uint32_t*)&t;
}

#define MMAF16(d, a, b0, b1)                                                \
    asm volatile("mma.sync.aligned.m16n8k16.row.col.f32.f16.f16.f32 "       \
        "{%0,%1,%2,%3}, {%4,%5,%6,%7}, {%8,%9}, {%0,%1,%2,%3};"             \
        : "+f"((d)[0]), "+f"((d)[1]), "+f"((d)[2]), "+f"((d)[3])            \
        : "r"((a)[0]), "r"((a)[1]), "r"((a)[2]), "r"((a)[3]),               \
          "r"(b0), "r"(b1))

// ---------------------------------------------------------------------------
// prep kernels
// ---------------------------------------------------------------------------
__global__ void prep_x(const float* __restrict__ x) {
    int i = (blockIdx.x * 256 + threadIdx.x) * 4;
    float4 v = *(const float4*)(x + i);
    *(half2*)&g_xh[i]     = __floats2half2_rn(v.x, v.y);
    *(half2*)&g_xh[i + 2] = __floats2half2_rn(v.z, v.w);
}

template<int WHICH>
__global__ void transp_w(const float* __restrict__ W) {
    __half* Wt = (WHICH == 0) ? g_wqkvT : g_woutT;
    const int N = (WHICH == 0) ? QKVN : DIMC;
    const int K = DIMC;
    __shared__ float t[32][33];
    const int n0 = blockIdx.x * 32, k0 = blockIdx.y * 32;
    for (int i = threadIdx.y; i < 32; i += 8)
        t[i][threadIdx.x] = W[(size_t)(k0 + i) * N + n0 + threadIdx.x];
    __syncthreads();
    for (int i = threadIdx.y; i < 32; i += 8)
        Wt[(size_t)(n0 + i) * K + k0 + threadIdx.x] =
            __float2half(t[threadIdx.x][i]);
}

// ===========================================================================
// HMMA fp16 GEMM (unchanged from R14, verified 93us): BM=BN=128, BK=64.
// ===========================================================================
#define GROW 144
#define GA_BYTES (128 * GROW)
#define GBUF (2 * GA_BYTES)
#define GEMM_SMEM (2 * GBUF)             // 73728
#define GNIT (DIMC / 64)                 // 12

template<int MODE>
__global__ __launch_bounds__(256, 2) void hmma_gemm(
    const float* __restrict__ bias, float* __restrict__ out)
{
    extern __shared__ char sg[];
    const uint32_t sb = smem_u32(sg);
    const int tid = threadIdx.x;
    const int lane = tid & 31, wid = tid >> 5;
    const int g = lane >> 2, qd = lane & 3;
    const int wm = wid >> 2, wn = wid & 3;
    const int rowBase = blockIdx.y * 128;
    const int colBase = blockIdx.x * 128;

    const __half* __restrict__ Ah = (MODE == 0) ? g_xh : g_aoh;
    const __half* __restrict__ Bt = (MODE == 0) ? g_wqkvT : g_woutT;

    float C[4][4][4] = {};

    const int lrA = lane & 15;
    const int lcA = (lane & 16) >> 1;
    const int lrB = ((lane & 16) >> 1) + (lane & 7);
    const int lcB = lane & 8;

    auto preload = [&](int buf, int k0) {
        const uint32_t ab = sb + buf * GBUF;
        #pragma unroll
        for (int j = 0; j < 4; j++) {
            int e = tid + j * 256;
            int r = e >> 3, c = e & 7;
            cp16(ab + r * GROW + c * 16, Ah + (size_t)(rowBase + r) * DIMC + k0 + c * 8);
        }
        const uint32_t bb2 = sb + buf * GBUF + GA_BYTES;
        #pragma unroll
        for (int j = 0; j < 4; j++) {
            int e = tid + j * 256;
            int n = e >> 3, c = e & 7;
            cp16(bb2 + n * GROW + c * 16, Bt + (size_t)(colBase + n) * DIMC + k0 + c * 8);
        }
    };

    auto domma = [&](int buf) {
        const uint32_t aBase = sb + buf * GBUF;
        const uint32_t bBase = aBase + GA_BYTES;
        #pragma unroll
        for (int kb = 0; kb < 4; kb++) {
            uint32_t a[4][4];
            #pragma unroll
            for (int mt = 0; mt < 4; mt++)
                LDSM4(a[mt][0], a[mt][1], a[mt][2], a[mt][3],
                      aBase + (wm * 64 + mt * 16 + lrA) * GROW
                            + (kb * 16 + lcA) * 2);
            #pragma unroll
            for (int ntp = 0; ntp < 2; ntp++) {
                uint32_t b0, b1, b2, b3;
                LDSM4(b0, b1, b2, b3,
                      bBase + (wn * 32 + ntp * 16 + lrB) * GROW
                            + (kb * 16 + lcB) * 2);
                #pragma unroll
                for (int mt = 0; mt < 4; mt++) {
                    MMAF16(C[mt][2 * ntp],     a[mt], b0, b1);
                    MMAF16(C[mt][2 * ntp + 1], a[mt], b2, b3);
                }
            }
        }
    };

    preload(0, 0);
    CP_COMMIT();
    for (int it = 0; it < GNIT; it++) {
        CP_WAIT0();
        __syncthreads();
        if (it + 1 < GNIT) {
            preload((it + 1) & 1, (it + 1) * 64);
            CP_COMMIT();
        }
        domma(it & 1);
    }

    if (MODE == 1) {
        #pragma unroll
        for (int mt = 0; mt < 4; mt++) {
            const int r0 = rowBase + wm * 64 + mt * 16 + g;
            #pragma unroll
            for (int nt = 0; nt < 4; nt++) {
                const int c0 = colBase + wn * 32 + nt * 8 + qd * 2;
                const float b0 = bias[c0], b1 = bias[c0 + 1];
                float2 v0 = make_float2(C[mt][nt][0] + b0, C[mt][nt][1] + b1);
                float2 v1 = make_float2(C[mt][nt][2] + b0, C[mt][nt][3] + b1);
                *(float2*)&out[(size_t)r0 * DIMC + c0] = v0;
                *(float2*)&out[(size_t)(r0 + 8) * DIMC + c0] = v1;
            }
        }
    } else {
        const int part = colBase / DIMC;
        #pragma unroll
        for (int mt = 0; mt < 4; mt++) {
            const int r0 = rowBase + wm * 64 + mt * 16 + g;
            #pragma unroll
            for (int nt = 0; nt < 4; nt++) {
                const int c0 = colBase + wn * 32 + nt * 8 + qd * 2;
                const int cc = c0 - part * DIMC;
                const int h = cc >> 6, dd = cc & 63;
                const float b0 = bias[c0], b1 = bias[c0 + 1];
                #pragma unroll
                for (int rr = 0; rr < 2; rr++) {
                    const int row = r0 + rr * 8;
                    const int bb = row >> 12, nn = row & 4095;
                    const size_t bhh = (size_t)(bb * HEADS + h);
                    float v0 = C[mt][nt][rr * 2]     + b0;
                    float v1 = C[mt][nt][rr * 2 + 1] + b1;
                    if (part == 0) {
                        *(half2*)&g_qh[(bhh * SEQ + nn) * DHC + dd] =
                            __floats2half2_rn(v0 * SCLOG2E, v1 * SCLOG2E);
                    } else if (part == 1) {
                        *(half2*)&g_kh[(bhh * SEQ + nn) * DHC + dd] =
                            __floats2half2_rn(v0, v1);
                    } else {
                        g_vth[(bhh * DHC + dd) * SEQ + nn]     = __float2half(v0);
                        g_vth[(bhh * DHC + dd + 1) * SEQ + nn] = __float2half(v1);
                    }
                }
            }
        }
    }
}

// ===========================================================================
// fp16 HMMA flash attention — 256-row Q tile, FUSED per-16-key-group
// pipeline: for each group t: S(t) MMAs -> ex2 -> PV(t) MMAs. The ex2 of
// group t overlaps PV MMAs of group t-1 in the warp's instruction window
// (in-warp ILP); S and P are fully transient (~150 regs). O/L accumulation
// order (kb=0..3) identical to R15 -> bit-identical result.
// 256 threads = 8 warps x 32 q-rows. Smem: Q 36864 + 3*18432 = 92160.
// ===========================================================================
#define AROW 144
#define AQ_BYTES 36864
#define AK_BYTES 9216
#define AKV 18432
#define AT_SMEM (AQ_BYTES + 3 * AKV)      // 92160
#define ANIT (SEQ / 64)                   // 64

__global__ __launch_bounds__(256) void attn_hmma() {
    extern __shared__ char smb[];
    const uint32_t sb = smem_u32(smb);
    const int tid = threadIdx.x;
    const int lane = tid & 31, wid = tid >> 5;
    const int g = lane >> 2, qd = lane & 3;
    const int bh = blockIdx.y;
    const int qbase = blockIdx.x * 256;
    const int wrow = wid * 32;

    const __half* qg = g_qh + ((size_t)bh * SEQ + qbase) * DHC;
    const __half* kg = g_kh + (size_t)bh * SEQ * DHC;
    const __half* vg = g_vth + (size_t)bh * DHC * SEQ;

    const int lr = ((lane & 16) >> 1) + (lane & 7);   // B tile row
    const int lc = lane & 8;                          // B tile col
    const int qr = lane & 15;                         // A tile row (in group)
    const int qc = (lane & 16) >> 1;                  // A tile col

    auto ldkv = [&](int buf, int kt) {
        const uint32_t kb_ = sb + AQ_BYTES + buf * AKV;
        #pragma unroll
        for (int j = 0; j < 2; j++) {
            int e = tid + j * 256;
            int r = e >> 3, c = e & 7;
            cp16(kb_ + r * AROW + c * 16, kg + (size_t)(kt + r) * DHC + c * 8);
        }
        const uint32_t vb_ = kb_ + AK_BYTES;
        #pragma unroll
        for (int j = 0; j < 2; j++) {
            int e = tid + j * 256;
            int r = e >> 3, c = e & 7;
            cp16(vb_ + r * AROW + c * 16, vg + (size_t)r * SEQ + kt + c * 8);
        }
    };

    // prologue: Q (256 x 64 halfs), then KV for iters 0 and 1
    #pragma unroll
    for (int j = 0; j < 8; j++) {
        int e = tid + j * 256;
        int r = e >> 3, c = e & 7;
        cp16(sb + r * AROW + c * 16, qg + (size_t)r * DHC + c * 8);
    }
    CP_COMMIT();
    ldkv(0, 0);  CP_COMMIT();
    ldkv(1, 64); CP_COMMIT();

    // Q fragments -> registers (loop-invariant), 2 groups of 16 rows
    CP_WAIT2();
    __syncthreads();
    uint32_t qa[2][4][4];
    #pragma unroll
    for (int mb = 0; mb < 2; mb++)
        #pragma unroll
        for (int kb = 0; kb < 4; kb++)
            LDSM4(qa[mb][kb][0], qa[mb][kb][1], qa[mb][kb][2], qa[mb][kb][3],
                  sb + (wrow + mb * 16 + qr) * AROW + (kb * 16 + qc) * 2);

    float O[2][8][4] = {};
    float L[2][4] = {};
    const uint32_t ONES = 0x3C003C00u;

    for (int it = 0; it < ANIT; it++) {
        if (it < ANIT - 1) { CP_WAIT1(); } else { CP_WAIT0(); }
        __syncthreads();
        if (it + 2 < ANIT) {
            ldkv((it + 2) % 3, (it + 2) * 64);
            CP_COMMIT();
        }

        const int buf = it % 3;
        const uint32_t kBase = sb + AQ_BYTES + buf * AKV;
        const uint32_t vBase = kBase + AK_BYTES;

        // ---- fused per-16-key-group pipeline: S(t) -> ex2 -> PV(t) ----
        #pragma unroll
        for (int t = 0; t < 4; t++) {
            // S for key group t (keys 16t..16t+15)
            float S0[2][4] = {};   // keys 16t..16t+7
            float S1[2][4] = {};   // keys 16t+8..16t+15
            #pragma unroll
            for (int kb = 0; kb < 4; kb++) {
                uint32_t b0, b1, b2, b3;
                LDSM4(b0, b1, b2, b3,
                      kBase + (t * 16 + lr) * AROW + (kb * 16 + lc) * 2);
                MMAF16(S0[0], qa[0][kb], b0, b1);
                MMAF16(S1[0], qa[0][kb], b2, b3);
                MMAF16(S0[1], qa[1][kb], b0, b1);
                MMAF16(S1[1], qa[1][kb], b2, b3);
            }
            // P = 2^S (transient, this group only)
            uint32_t P[2][4];
            #pragma unroll
            for (int mb = 0; mb < 2; mb++) {
                P[mb][0] = ex2h2(pack2h(S0[mb][0], S0[mb][1]));
                P[mb][1] = ex2h2(pack2h(S0[mb][2], S0[mb][3]));
                P[mb][2] = ex2h2(pack2h(S1[mb][0], S1[mb][1]));
                P[mb][3] = ex2h2(pack2h(S1[mb][2], S1[mb][3]));
            }
            // L and PV for this key group (V^T columns 16t..16t+15)
            MMAF16(L[0], P[0], ONES, ONES);
            MMAF16(L[1], P[1], ONES, ONES);
            #pragma unroll
            for (int nbp = 0; nbp < 4; nbp++) {
                uint32_t b0, b1, b2, b3;
                LDSM4(b0, b1, b2, b3,
                      vBase + (nbp * 16 + lr) * AROW + (t * 16 + lc) * 2);
                #pragma unroll
                for (int mb = 0; mb < 2; mb++) {
                    MMAF16(O[mb][2 * nbp],     P[mb], b0, b1);
                    MMAF16(O[mb][2 * nbp + 1], P[mb], b2, b3);
                }
            }
        }
    }

    // ---- epilogue: O / L -> g_aoh ----
    const int bb = bh / HEADS, h = bh % HEADS;
    #pragma unroll
    for (int mb = 0; mb < 2; mb++) {
        const float i0 = 1.0f / L[mb][0];
        const float i1 = 1.0f / L[mb][2];
        const int r0 = qbase + wrow + mb * 16 + g;
        #pragma unroll
        for (int nb = 0; nb < 8; nb++) {
            const int col = h * DHC + nb * 8 + qd * 2;
            *(half2*)&g_aoh[((size_t)(bb * SEQ + r0)) * DIMC + col] =
                __floats2half2_rn(O[mb][nb][0] * i0, O[mb][nb][1] * i0);
            *(half2*)&g_aoh[((size_t)(bb * SEQ + r0 + 8)) * DIMC + col] =
                __floats2half2_rn(O[mb][nb][2] * i1, O[mb][nb][3] * i1);
        }
    }
}

// ---------------------------------------------------------------------------
extern "C" void kernel_launch(void* const* d_in, const int* in_sizes, int n_in,
                              void* d_out, int out_size) {
    const float* x     = (const float*)d_in[0];
    const float* w_qkv = (const float*)d_in[1];
    const float* b_qkv = (const float*)d_in[2];
    const float* w_out = (const float*)d_in[3];
    const float* b_out = (const float*)d_in[4];
    float* out = (float*)d_out;

    cudaFuncSetAttribute(hmma_gemm<0>,
                         cudaFuncAttributeMaxDynamicSharedMemorySize, GEMM_SMEM);
    cudaFuncSetAttribute(hmma_gemm<1>,
                         cudaFuncAttributeMaxDynamicSharedMemorySize, GEMM_SMEM);
    cudaFuncSetAttribute(attn_hmma,
                         cudaFuncAttributeMaxDynamicSharedMemorySize, AT_SMEM);

    prep_x<<<TOKENS * DIMC / 1024, 256>>>(x);
    transp_w<0><<<dim3(QKVN / 32, DIMC / 32), dim3(32, 8)>>>(w_qkv);
    transp_w<1><<<dim3(DIMC / 32, DIMC / 32), dim3(32, 8)>>>(w_out);

    hmma_gemm<0><<<dim3(QKVN / 128, TOKENS / 128), 256, GEMM_SMEM>>>(b_qkv, nullptr);

    attn_hmma<<<dim3(SEQ / 256, BATCH * HEADS), 256, AT_SMEM>>>();

    hmma_gemm<1><<<dim3(DIMC / 128, TOKENS / 128), 256, GEMM_SMEM>>>(b_out, out);
}

// round 17
// speedup vs baseline: 1.0689x; 1.0689x over previous
#include <cuda_runtime.h>
#include <cuda_fp16.h>
#include <cstdint>

#define DIMC   768
#define HEADS  12
#define DHC    64
#define BATCH  2
#define SEQ    4096
#define TOKENS (BATCH * SEQ)     // 8192
#define QKVN   (3 * DIMC)        // 2304
#define SCLOG2E 0.05205877693f   // 768^-0.5 * log2(e); folded into Q

// ---------------------------------------------------------------------------
// Scratch (device-code references only). All single fp16.
// ---------------------------------------------------------------------------
__device__ __half g_xh   [(size_t)TOKENS * DIMC];
__device__ __half g_wqkvT[(size_t)QKVN * DIMC];            // [N][K]
__device__ __half g_woutT[(size_t)DIMC * DIMC];
__device__ __half g_qh   [(size_t)BATCH * HEADS * SEQ * DHC];  // Q*SCLOG2E
__device__ __half g_kh   [(size_t)BATCH * HEADS * SEQ * DHC];
__device__ __half g_vth  [(size_t)BATCH * HEADS * DHC * SEQ];  // V^T
__device__ __half g_aoh  [(size_t)TOKENS * DIMC];

// ---------------------------------------------------------------------------
__device__ __forceinline__ uint32_t smem_u32(const void* p) {
    uint32_t a;
    asm("{ .reg .u64 t; cvta.to.shared.u64 t, %1; cvt.u32.u64 %0, t; }"
        : "=r"(a) : "l"(p));
    return a;
}
__device__ __forceinline__ void cp16(uint32_t dst, const void* src) {
    asm volatile("cp.async.cg.shared.global [%0], [%1], 16;"
                 :: "r"(dst), "l"(src));
}
#define CP_COMMIT() asm volatile("cp.async.commit_group;" ::: "memory")
#define CP_WAIT0()  asm volatile("cp.async.wait_group 0;" ::: "memory")
#define CP_WAIT1()  asm volatile("cp.async.wait_group 1;" ::: "memory")

#define LDSM4(R0, R1, R2, R3, ADDR)                                         \
    asm volatile("ldmatrix.sync.aligned.m8n8.x4.shared.b16 "                \
        "{%0,%1,%2,%3}, [%4];"                                              \
        : "=r"(R0), "=r"(R1), "=r"(R2), "=r"(R3) : "r"(ADDR))

__device__ __forceinline__ uint32_t ex2h2(uint32_t y) {
    uint32_t r;
    asm("ex2.approx.f16x2 %0, %1;" : "=r"(r) : "r"(y));
    return r;
}
__device__ __forceinline__ uint32_t pack2h(float x, float y) {
    __half2 t = __floats2half2_rn(x, y);
    return *(uint32_t*)&t;
}

#define MMAF16(d, a, b0, b1)                                                \
    asm volatile("mma.sync.aligned.m16n8k16.row.col.f32.f16.f16.f32 "       \
        "{%0,%1,%2,%3}, {%4,%5,%6,%7}, {%8,%9}, {%0,%1,%2,%3};"             \
        : "+f"((d)[0]), "+f"((d)[1]), "+f"((d)[2]), "+f"((d)[3])            \
        : "r"((a)[0]), "r"((a)[1]), "r"((a)[2]), "r"((a)[3]),               \
          "r"(b0), "r"(b1))

// ---------------------------------------------------------------------------
// merged prep kernel: x->fp16 | w_qkv^T->fp16 | w_out^T->fp16, one launch
// ---------------------------------------------------------------------------
#define PX_BLOCKS (TOKENS * DIMC / 1024)          // 6144
#define T0_BLOCKS ((QKVN / 32) * (DIMC / 32))     // 1728
#define T1_BLOCKS ((DIMC / 32) * (DIMC / 32))     // 576
#define PREP_BLOCKS (PX_BLOCKS + T0_BLOCKS + T1_BLOCKS)  // 8448

__global__ __launch_bounds__(256) void prep_all(const float* __restrict__ x,
                                                const float* __restrict__ wq,
                                                const float* __restrict__ wo) {
    __shared__ float t[32][33];
    const int b = blockIdx.x;
    const int tid = threadIdx.x;

    if (b < PX_BLOCKS) {
        int i = (b * 256 + tid) * 4;
        float4 v = *(const float4*)(x + i);
        *(half2*)&g_xh[i]     = __floats2half2_rn(v.x, v.y);
        *(half2*)&g_xh[i + 2] = __floats2half2_rn(v.z, v.w);
        return;
    }
    const float* W;
    __half* Wt;
    int N, bx, by;
    if (b < PX_BLOCKS + T0_BLOCKS) {
        int b2 = b - PX_BLOCKS;
        W = wq; Wt = g_wqkvT; N = QKVN;
        bx = b2 % (QKVN / 32); by = b2 / (QKVN / 32);
    } else {
        int b2 = b - PX_BLOCKS - T0_BLOCKS;
        W = wo; Wt = g_woutT; N = DIMC;
        bx = b2 % (DIMC / 32); by = b2 / (DIMC / 32);
    }
    const int tx = tid & 31, ty = tid >> 5;
    const int n0 = bx * 32, k0 = by * 32;
    for (int i = ty; i < 32; i += 8)
        t[i][tx] = W[(size_t)(k0 + i) * N + n0 + tx];
    __syncthreads();
    for (int i = ty; i < 32; i += 8)
        Wt[(size_t)(n0 + i) * DIMC + k0 + tx] = __float2half(t[tx][i]);
}

// ===========================================================================
// HMMA fp16 GEMM (unchanged, verified 93us): BM=BN=128, BK=64, 2-stage ring.
// ===========================================================================
#define GROW 144
#define GA_BYTES (128 * GROW)
#define GBUF (2 * GA_BYTES)
#define GEMM_SMEM (2 * GBUF)             // 73728
#define GNIT (DIMC / 64)                 // 12

template<int MODE>
__global__ __launch_bounds__(256, 2) void hmma_gemm(
    const float* __restrict__ bias, float* __restrict__ out)
{
    extern __shared__ char sg[];
    const uint32_t sb = smem_u32(sg);
    const int tid = threadIdx.x;
    const int lane = tid & 31, wid = tid >> 5;
    const int g = lane >> 2, qd = lane & 3;
    const int wm = wid >> 2, wn = wid & 3;
    const int rowBase = blockIdx.y * 128;
    const int colBase = blockIdx.x * 128;

    const __half* __restrict__ Ah = (MODE == 0) ? g_xh : g_aoh;
    const __half* __restrict__ Bt = (MODE == 0) ? g_wqkvT : g_woutT;

    float C[4][4][4] = {};

    const int lrA = lane & 15;
    const int lcA = (lane & 16) >> 1;
    const int lrB = ((lane & 16) >> 1) + (lane & 7);
    const int lcB = lane & 8;

    auto preload = [&](int buf, int k0) {
        const uint32_t ab = sb + buf * GBUF;
        #pragma unroll
        for (int j = 0; j < 4; j++) {
            int e = tid + j * 256;
            int r = e >> 3, c = e & 7;
            cp16(ab + r * GROW + c * 16, Ah + (size_t)(rowBase + r) * DIMC + k0 + c * 8);
        }
        const uint32_t bb2 = sb + buf * GBUF + GA_BYTES;
        #pragma unroll
        for (int j = 0; j < 4; j++) {
            int e = tid + j * 256;
            int n = e >> 3, c = e & 7;
            cp16(bb2 + n * GROW + c * 16, Bt + (size_t)(colBase + n) * DIMC + k0 + c * 8);
        }
    };

    auto domma = [&](int buf) {
        const uint32_t aBase = sb + buf * GBUF;
        const uint32_t bBase = aBase + GA_BYTES;
        #pragma unroll
        for (int kb = 0; kb < 4; kb++) {
            uint32_t a[4][4];
            #pragma unroll
            for (int mt = 0; mt < 4; mt++)
                LDSM4(a[mt][0], a[mt][1], a[mt][2], a[mt][3],
                      aBase + (wm * 64 + mt * 16 + lrA) * GROW
                            + (kb * 16 + lcA) * 2);
            #pragma unroll
            for (int ntp = 0; ntp < 2; ntp++) {
                uint32_t b0, b1, b2, b3;
                LDSM4(b0, b1, b2, b3,
                      bBase + (wn * 32 + ntp * 16 + lrB) * GROW
                            + (kb * 16 + lcB) * 2);
                #pragma unroll
                for (int mt = 0; mt < 4; mt++) {
                    MMAF16(C[mt][2 * ntp],     a[mt], b0, b1);
                    MMAF16(C[mt][2 * ntp + 1], a[mt], b2, b3);
                }
            }
        }
    };

    preload(0, 0);
    CP_COMMIT();
    for (int it = 0; it < GNIT; it++) {
        CP_WAIT0();
        __syncthreads();
        if (it + 1 < GNIT) {
            preload((it + 1) & 1, (it + 1) * 64);
            CP_COMMIT();
        }
        domma(it & 1);
    }

    if (MODE == 1) {
        #pragma unroll
        for (int mt = 0; mt < 4; mt++) {
            const int r0 = rowBase + wm * 64 + mt * 16 + g;
            #pragma unroll
            for (int nt = 0; nt < 4; nt++) {
                const int c0 = colBase + wn * 32 + nt * 8 + qd * 2;
                const float b0 = bias[c0], b1 = bias[c0 + 1];
                float2 v0 = make_float2(C[mt][nt][0] + b0, C[mt][nt][1] + b1);
                float2 v1 = make_float2(C[mt][nt][2] + b0, C[mt][nt][3] + b1);
                *(float2*)&out[(size_t)r0 * DIMC + c0] = v0;
                *(float2*)&out[(size_t)(r0 + 8) * DIMC + c0] = v1;
            }
        }
    } else {
        const int part = colBase / DIMC;
        #pragma unroll
        for (int mt = 0; mt < 4; mt++) {
            const int r0 = rowBase + wm * 64 + mt * 16 + g;
            #pragma unroll
            for (int nt = 0; nt < 4; nt++) {
                const int c0 = colBase + wn * 32 + nt * 8 + qd * 2;
                const int cc = c0 - part * DIMC;
                const int h = cc >> 6, dd = cc & 63;
                const float b0 = bias[c0], b1 = bias[c0 + 1];
                #pragma unroll
                for (int rr = 0; rr < 2; rr++) {
                    const int row = r0 + rr * 8;
                    const int bb = row >> 12, nn = row & 4095;
                    const size_t bhh = (size_t)(bb * HEADS + h);
                    float v0 = C[mt][nt][rr * 2]     + b0;
                    float v1 = C[mt][nt][rr * 2 + 1] + b1;
                    if (part == 0) {
                        *(half2*)&g_qh[(bhh * SEQ + nn) * DHC + dd] =
                            __floats2half2_rn(v0 * SCLOG2E, v1 * SCLOG2E);
                    } else if (part == 1) {
                        *(half2*)&g_kh[(bhh * SEQ + nn) * DHC + dd] =
                            __floats2half2_rn(v0, v1);
                    } else {
                        g_vth[(bhh * DHC + dd) * SEQ + nn]     = __float2half(v0);
                        g_vth[(bhh * DHC + dd + 1) * SEQ + nn] = __float2half(v1);
                    }
                }
            }
        }
    }
}

// ===========================================================================
// fp16 HMMA flash attention — 256-row Q tile, Q frags via direct LDG (no Q
// smem), 6-slot KV ring (3 pairs), ONE sync per 2 tiles (de-phase-lock).
// Fused per-16-key-group S->ex2->PV. 256 threads = 8 warps x 32 q-rows.
// Smem: 6 * 18432 = 110592.
// ===========================================================================
#define AROW 144
#define AK_BYTES 9216
#define AKV 18432
#define AT_SMEM (6 * AKV)                 // 110592
#define ANPAIR (SEQ / 128)                // 32 pairs of 64-key tiles

__global__ __launch_bounds__(256) void attn_hmma() {
    extern __shared__ char smb[];
    const uint32_t sb = smem_u32(smb);
    const int tid = threadIdx.x;
    const int lane = tid & 31, wid = tid >> 5;
    const int g = lane >> 2, qd = lane & 3;
    const int bh = blockIdx.y;
    const int qbase = blockIdx.x * 256;
    const int wrow = wid * 32;

    const __half* qg = g_qh + ((size_t)bh * SEQ + qbase) * DHC;
    const __half* kg = g_kh + (size_t)bh * SEQ * DHC;
    const __half* vg = g_vth + (size_t)bh * DHC * SEQ;

    const int lr = ((lane & 16) >> 1) + (lane & 7);   // B tile row
    const int lc = lane & 8;                          // B tile col

    auto ldkv = [&](int slot, int kt) {
        const uint32_t kb_ = sb + slot * AKV;
        #pragma unroll
        for (int j = 0; j < 2; j++) {
            int e = tid + j * 256;
            int r = e >> 3, c = e & 7;
            cp16(kb_ + r * AROW + c * 16, kg + (size_t)(kt + r) * DHC + c * 8);
        }
        const uint32_t vb_ = kb_ + AK_BYTES;
        #pragma unroll
        for (int j = 0; j < 2; j++) {
            int e = tid + j * 256;
            int r = e >> 3, c = e & 7;
            cp16(vb_ + r * AROW + c * 16, vg + (size_t)r * SEQ + kt + c * 8);
        }
    };

    // Q fragments via direct LDG (A-fragment lane mapping; one-time)
    uint32_t qa[2][4][4];
    #pragma unroll
    for (int mb = 0; mb < 2; mb++) {
        const __half* q0 = qg + (size_t)(wrow + mb * 16 + g) * DHC;
        const __half* q8 = q0 + 8 * DHC;
        #pragma unroll
        for (int kb = 0; kb < 4; kb++) {
            qa[mb][kb][0] = *(const uint32_t*)(q0 + kb * 16 + qd * 2);
            qa[mb][kb][1] = *(const uint32_t*)(q8 + kb * 16 + qd * 2);
            qa[mb][kb][2] = *(const uint32_t*)(q0 + kb * 16 + 8 + qd * 2);
            qa[mb][kb][3] = *(const uint32_t*)(q8 + kb * 16 + 8 + qd * 2);
        }
    }

    // prologue: pairs 0 (tiles 0,1) and 1 (tiles 2,3)
    ldkv(0, 0);   ldkv(1, 64);  CP_COMMIT();
    ldkv(2, 128); ldkv(3, 192); CP_COMMIT();

    float O[2][8][4] = {};
    float L[2][4] = {};
    const uint32_t ONES = 0x3C003C00u;

    // fused per-16-key-group pipeline over one 64-key tile in 'slot'
    auto process = [&](int slot) {
        const uint32_t kBase = sb + slot * AKV;
        const uint32_t vBase = kBase + AK_BYTES;
        #pragma unroll
        for (int t = 0; t < 4; t++) {
            float S0[2][4] = {};
            float S1[2][4] = {};
            #pragma unroll
            for (int kb = 0; kb < 4; kb++) {
                uint32_t b0, b1, b2, b3;
                LDSM4(b0, b1, b2, b3,
                      kBase + (t * 16 + lr) * AROW + (kb * 16 + lc) * 2);
                MMAF16(S0[0], qa[0][kb], b0, b1);
                MMAF16(S1[0], qa[0][kb], b2, b3);
                MMAF16(S0[1], qa[1][kb], b0, b1);
                MMAF16(S1[1], qa[1][kb], b2, b3);
            }
            uint32_t P[2][4];
            #pragma unroll
            for (int mb = 0; mb < 2; mb++) {
                P[mb][0] = ex2h2(pack2h(S0[mb][0], S0[mb][1]));
                P[mb][1] = ex2h2(pack2h(S0[mb][2], S0[mb][3]));
                P[mb][2] = ex2h2(pack2h(S1[mb][0], S1[mb][1]));
                P[mb][3] = ex2h2(pack2h(S1[mb][2], S1[mb][3]));
            }
            MMAF16(L[0], P[0], ONES, ONES);
            MMAF16(L[1], P[1], ONES, ONES);
            #pragma unroll
            for (int nbp = 0; nbp < 4; nbp++) {
                uint32_t b0, b1, b2, b3;
                LDSM4(b0, b1, b2, b3,
                      vBase + (nbp * 16 + lr) * AROW + (t * 16 + lc) * 2);
                #pragma unroll
                for (int mb = 0; mb < 2; mb++) {
                    MMAF16(O[mb][2 * nbp],     P[mb], b0, b1);
                    MMAF16(O[mb][2 * nbp + 1], P[mb], b2, b3);
                }
            }
        }
    };

    for (int j = 0; j < ANPAIR; j++) {
        if (j < ANPAIR - 1) { CP_WAIT1(); } else { CP_WAIT0(); }
        __syncthreads();
        if (j + 2 < ANPAIR) {
            const int p = (j + 2) % 3;
            ldkv(p * 2,     (2 * j + 4) * 64);
            ldkv(p * 2 + 1, (2 * j + 5) * 64);
            CP_COMMIT();
        }
        const int p = j % 3;
        process(p * 2);
        process(p * 2 + 1);
    }

    // ---- epilogue: O / L -> g_aoh ----
    const int bb = bh / HEADS, h = bh % HEADS;
    #pragma unroll
    for (int mb = 0; mb < 2; mb++) {
        const float i0 = 1.0f / L[mb][0];
        const float i1 = 1.0f / L[mb][2];
        const int r0 = qbase + wrow + mb * 16 + g;
        #pragma unroll
        for (int nb = 0; nb < 8; nb++) {
            const int col = h * DHC + nb * 8 + qd * 2;
            *(half2*)&g_aoh[((size_t)(bb * SEQ + r0)) * DIMC + col] =
                __floats2half2_rn(O[mb][nb][0] * i0, O[mb][nb][1] * i0);
            *(half2*)&g_aoh[((size_t)(bb * SEQ + r0 + 8)) * DIMC + col] =
                __floats2half2_rn(O[mb][nb][2] * i1, O[mb][nb][3] * i1);
        }
    }
}

// ---------------------------------------------------------------------------
extern "C" void kernel_launch(void* const* d_in, const int* in_sizes, int n_in,
                              void* d_out, int out_size) {
    const float* x     = (const float*)d_in[0];
    const float* w_qkv = (const float*)d_in[1];
    const float* b_qkv = (const float*)d_in[2];
    const float* w_out = (const float*)d_in[3];
    const float* b_out = (const float*)d_in[4];
    float* out = (float*)d_out;

    cudaFuncSetAttribute(hmma_gemm<0>,
                         cudaFuncAttributeMaxDynamicSharedMemorySize, GEMM_SMEM);
    cudaFuncSetAttribute(hmma_gemm<1>,
                         cudaFuncAttributeMaxDynamicSharedMemorySize, GEMM_SMEM);
    cudaFuncSetAttribute(attn_hmma,
                         cudaFuncAttributeMaxDynamicSharedMemorySize, AT_SMEM);

    prep_all<<<PREP_BLOCKS, 256>>>(x, w_qkv, w_out);

    hmma_gemm<0><<<dim3(QKVN / 128, TOKENS / 128), 256, GEMM_SMEM>>>(b_qkv, nullptr);

    attn_hmma<<<dim3(SEQ / 256, BATCH * HEADS), 256, AT_SMEM>>>();

    hmma_gemm<1><<<dim3(DIMC / 128, TOKENS / 128), 256, GEMM_SMEM>>>(b_out, out);
}